// round 2
// baseline (speedup 1.0000x reference)
#include <cuda_runtime.h>
#include <cstdint>

// ============================================================================
// ViTMAE attention block: B=16, S=1024, HID=1024, HEADS=16, D=64, fp32.
//   q = x@Wq + bq ; k = x@Wk + bk ; v = x@Wv + bv      (scatter to [B,H,S,D])
//   ctx = softmax(q k^T / 8) v                          (fused, flash-style)
//   out = ctx@Wd + bd                                   ([B,S,HID])
// ============================================================================

#define BATCH   16
#define SEQ     1024
#define HID     1024
#define HEADS   16
#define HDIM    64
#define MROWS   (BATCH * SEQ)   // 16384

// Scratch (module-load static device allocations; referenced directly by
// kernels so kernel_launch contains nothing but kernel launches).
__device__ float g_q[(size_t)BATCH * HEADS * SEQ * HDIM];
__device__ float g_k[(size_t)BATCH * HEADS * SEQ * HDIM];
__device__ float g_v[(size_t)BATCH * HEADS * SEQ * HDIM];
__device__ float g_ctx[(size_t)MROWS * HID];

// ----------------------------------------------------------------------------
// SGEMM: C[M,N] = A[M,K] @ W[K,N] + bias[N]
// BM=128, BN=128, BK=16, 256 threads, 8x8 register tile per thread.
// MODE 0: A = g_ctx,  out = arg (row-major [M,N])
// MODE 1: A = arg,    out = one of g_q/g_k/g_v selected by `which`,
//                     scattered to [B,H,S,D] layout.
// ----------------------------------------------------------------------------
template <int MODE>
__global__ __launch_bounds__(256) void sgemm_kernel(
    const float* __restrict__ Ain, const float* __restrict__ W,
    const float* __restrict__ bias, float* __restrict__ outArg, int which)
{
    const int K = HID, N = HID;
    __shared__ float As[16][128];      // transposed: As[k][m]
    __shared__ float Bs[16][128];      // Bs[k][n]

    const float* A = (MODE == 0) ? g_ctx : Ain;
    float* out;
    if (MODE == 0) out = outArg;
    else           out = (which == 0) ? g_q : (which == 1) ? g_k : g_v;

    const int tid = threadIdx.x;
    const int ty = tid / 16, tx = tid % 16;
    const int row0 = blockIdx.y * 128;
    const int col0 = blockIdx.x * 128;

    // A-tile load mapping: 128 rows x 16 cols = 512 float4, 2 per thread
    const int aRow = tid / 4;            // 0..63 (+64)
    const int aCol = (tid % 4) * 4;
    // B-tile load mapping: 16 rows x 128 cols = 512 float4, 2 per thread
    const int bRow = tid / 32;           // 0..7 (+8)
    const int bCol = (tid % 32) * 4;

    float acc[8][8];
#pragma unroll
    for (int i = 0; i < 8; i++)
#pragma unroll
        for (int j = 0; j < 8; j++) acc[i][j] = 0.f;

    for (int k0 = 0; k0 < K; k0 += 16) {
#pragma unroll
        for (int i = 0; i < 2; i++) {
            int r = aRow + i * 64;
            float4 va = *(const float4*)&A[(size_t)(row0 + r) * K + k0 + aCol];
            As[aCol + 0][r] = va.x;
            As[aCol + 1][r] = va.y;
            As[aCol + 2][r] = va.z;
            As[aCol + 3][r] = va.w;
        }
#pragma unroll
        for (int i = 0; i < 2; i++) {
            int r = bRow + i * 8;
            *(float4*)&Bs[r][bCol] =
                *(const float4*)&W[(size_t)(k0 + r) * N + col0 + bCol];
        }
        __syncthreads();

#pragma unroll
        for (int kk = 0; kk < 16; kk++) {
            float a[8], b[8];
            float4 a0 = *(const float4*)&As[kk][ty * 8];
            float4 a1 = *(const float4*)&As[kk][ty * 8 + 4];
            float4 b0 = *(const float4*)&Bs[kk][tx * 8];
            float4 b1 = *(const float4*)&Bs[kk][tx * 8 + 4];
            a[0]=a0.x; a[1]=a0.y; a[2]=a0.z; a[3]=a0.w;
            a[4]=a1.x; a[5]=a1.y; a[6]=a1.z; a[7]=a1.w;
            b[0]=b0.x; b[1]=b0.y; b[2]=b0.z; b[3]=b0.w;
            b[4]=b1.x; b[5]=b1.y; b[6]=b1.z; b[7]=b1.w;
#pragma unroll
            for (int i = 0; i < 8; i++)
#pragma unroll
                for (int j = 0; j < 8; j++) acc[i][j] += a[i] * b[j];
        }
        __syncthreads();
    }

    // Epilogue
#pragma unroll
    for (int i = 0; i < 8; i++) {
        int m = row0 + ty * 8 + i;
        int bb = m >> 10;            // batch
        int s  = m & 1023;           // seq pos
#pragma unroll
        for (int j = 0; j < 8; j += 4) {
            int col = col0 + tx * 8 + j;
            float4 v;
            v.x = acc[i][j + 0] + bias[col + 0];
            v.y = acc[i][j + 1] + bias[col + 1];
            v.z = acc[i][j + 2] + bias[col + 2];
            v.w = acc[i][j + 3] + bias[col + 3];
            if (MODE == 0) {
                *(float4*)&out[(size_t)m * N + col] = v;
            } else {
                int h = col >> 6, d = col & 63;   // 8-col group never crosses a head
                *(float4*)&out[(((size_t)bb * HEADS + h) * SEQ + s) * HDIM + d] = v;
            }
        }
    }
}

// ----------------------------------------------------------------------------
// Fused attention (flash-style, online softmax).
// Grid: (qtile=16, h=16, b=16). Block: 256 threads.
// Br=64 query rows, Bc=32 key rows per iteration, D=64.
// Thread map (ty=tid/16, tx=tid%16):
//   stage1 (QK^T): rows ty*4..+3, cols tx*2..+1
//   stage2 (PV):   rows ty*4..+3, dims tx*4..+3
// ctx written to g_ctx in [B, S, HID] layout for the final dense GEMM.
// ----------------------------------------------------------------------------
__global__ __launch_bounds__(256) void attn_kernel()
{
    __shared__ float Qs[64][65];
    __shared__ float Ks[32][65];
    __shared__ float Vs[32][64];
    __shared__ float Ps[64][33];
    __shared__ float m_s[64], l_s[64], corr_s[64];

    const int tid = threadIdx.x;
    const int ty = tid / 16, tx = tid % 16;
    const int qt = blockIdx.x, h = blockIdx.y, b = blockIdx.z;
    const size_t bh = (size_t)b * HEADS + h;
    const float* __restrict__ qb = g_q + (bh * SEQ + qt * 64) * HDIM;
    const float* __restrict__ kb = g_k + bh * SEQ * HDIM;
    const float* __restrict__ vb = g_v + bh * SEQ * HDIM;

    // Load Q tile: 64x64 floats = 1024 float4, 4 per thread
    for (int idx = tid; idx < 64 * 16; idx += 256) {
        int r = idx / 16, c4 = (idx % 16) * 4;
        float4 val = *(const float4*)&qb[r * HDIM + c4];
        Qs[r][c4 + 0] = val.x; Qs[r][c4 + 1] = val.y;
        Qs[r][c4 + 2] = val.z; Qs[r][c4 + 3] = val.w;
    }
    if (tid < 64) { m_s[tid] = -1e30f; l_s[tid] = 0.f; }

    float o[4][4];
#pragma unroll
    for (int i = 0; i < 4; i++)
#pragma unroll
        for (int j = 0; j < 4; j++) o[i][j] = 0.f;

    const float scale = 0.125f;   // 1/sqrt(64)
    __syncthreads();

    for (int kc = 0; kc < SEQ; kc += 32) {
        // Load K,V tiles: 32x64 each = 512 float4 each, 2+2 per thread
        for (int idx = tid; idx < 32 * 16; idx += 256) {
            int r = idx / 16, c4 = (idx % 16) * 4;
            float4 kv = *(const float4*)&kb[(size_t)(kc + r) * HDIM + c4];
            Ks[r][c4 + 0] = kv.x; Ks[r][c4 + 1] = kv.y;
            Ks[r][c4 + 2] = kv.z; Ks[r][c4 + 3] = kv.w;
            float4 vv = *(const float4*)&vb[(size_t)(kc + r) * HDIM + c4];
            *(float4*)&Vs[r][c4] = vv;
        }
        __syncthreads();

        // stage1: S = Q K^T * scale  -> Ps
        {
            float sc[4][2];
#pragma unroll
            for (int i = 0; i < 4; i++) { sc[i][0] = 0.f; sc[i][1] = 0.f; }
#pragma unroll
            for (int kk = 0; kk < 64; kk++) {
                float a0 = Qs[ty * 4 + 0][kk];
                float a1 = Qs[ty * 4 + 1][kk];
                float a2 = Qs[ty * 4 + 2][kk];
                float a3 = Qs[ty * 4 + 3][kk];
                float b0 = Ks[tx * 2 + 0][kk];
                float b1 = Ks[tx * 2 + 1][kk];
                sc[0][0] += a0 * b0; sc[0][1] += a0 * b1;
                sc[1][0] += a1 * b0; sc[1][1] += a1 * b1;
                sc[2][0] += a2 * b0; sc[2][1] += a2 * b1;
                sc[3][0] += a3 * b0; sc[3][1] += a3 * b1;
            }
#pragma unroll
            for (int i = 0; i < 4; i++) {
                Ps[ty * 4 + i][tx * 2 + 0] = sc[i][0] * scale;
                Ps[ty * 4 + i][tx * 2 + 1] = sc[i][1] * scale;
            }
        }
        __syncthreads();

        // softmax per row (threads 0..63 each own one row)
        if (tid < 64) {
            float m_old = m_s[tid];
            float mx = m_old;
#pragma unroll
            for (int c = 0; c < 32; c++) mx = fmaxf(mx, Ps[tid][c]);
            float corr = __expf(m_old - mx);
            float sum = 0.f;
#pragma unroll
            for (int c = 0; c < 32; c++) {
                float e = __expf(Ps[tid][c] - mx);
                Ps[tid][c] = e;
                sum += e;
            }
            m_s[tid] = mx;
            l_s[tid] = l_s[tid] * corr + sum;
            corr_s[tid] = corr;
        }
        __syncthreads();

        // stage2: O = O*corr + P V
        {
            float c0 = corr_s[ty * 4 + 0];
            float c1 = corr_s[ty * 4 + 1];
            float c2 = corr_s[ty * 4 + 2];
            float c3 = corr_s[ty * 4 + 3];
#pragma unroll
            for (int j = 0; j < 4; j++) {
                o[0][j] *= c0; o[1][j] *= c1; o[2][j] *= c2; o[3][j] *= c3;
            }
#pragma unroll
            for (int c = 0; c < 32; c++) {
                float p0 = Ps[ty * 4 + 0][c];
                float p1 = Ps[ty * 4 + 1][c];
                float p2 = Ps[ty * 4 + 2][c];
                float p3 = Ps[ty * 4 + 3][c];
                float4 vv = *(const float4*)&Vs[c][tx * 4];
                o[0][0] += p0 * vv.x; o[0][1] += p0 * vv.y; o[0][2] += p0 * vv.z; o[0][3] += p0 * vv.w;
                o[1][0] += p1 * vv.x; o[1][1] += p1 * vv.y; o[1][2] += p1 * vv.z; o[1][3] += p1 * vv.w;
                o[2][0] += p2 * vv.x; o[2][1] += p2 * vv.y; o[2][2] += p2 * vv.z; o[2][3] += p2 * vv.w;
                o[3][0] += p3 * vv.x; o[3][1] += p3 * vv.y; o[3][2] += p3 * vv.z; o[3][3] += p3 * vv.w;
            }
        }
        __syncthreads();
    }

    // normalize and write ctx in [B, S, HID] layout
    if (tid < 64) corr_s[tid] = 1.f / l_s[tid];
    __syncthreads();

#pragma unroll
    for (int i = 0; i < 4; i++) {
        int r = ty * 4 + i;
        float inv = corr_s[r];
        float4 w;
        w.x = o[i][0] * inv; w.y = o[i][1] * inv;
        w.z = o[i][2] * inv; w.w = o[i][3] * inv;
        size_t off = ((size_t)b * SEQ + qt * 64 + r) * HID + h * HDIM + tx * 4;
        *(float4*)&g_ctx[off] = w;
    }
}

// ----------------------------------------------------------------------------
extern "C" void kernel_launch(void* const* d_in, const int* in_sizes, int n_in,
                              void* d_out, int out_size)
{
    const float* hs = (const float*)d_in[0];
    const float* Wq = (const float*)d_in[1];
    const float* bq = (const float*)d_in[2];
    const float* Wk = (const float*)d_in[3];
    const float* bk = (const float*)d_in[4];
    const float* Wv = (const float*)d_in[5];
    const float* bv = (const float*)d_in[6];
    const float* Wd = (const float*)d_in[7];
    const float* bd = (const float*)d_in[8];

    dim3 gemmGrid(HID / 128, MROWS / 128);   // (8, 128)
    sgemm_kernel<1><<<gemmGrid, 256>>>(hs, Wq, bq, nullptr, 0);
    sgemm_kernel<1><<<gemmGrid, 256>>>(hs, Wk, bk, nullptr, 1);
    sgemm_kernel<1><<<gemmGrid, 256>>>(hs, Wv, bv, nullptr, 2);

    attn_kernel<<<dim3(SEQ / 64, HEADS, BATCH), 256>>>();

    sgemm_kernel<0><<<gemmGrid, 256>>>(nullptr, Wd, bd, (float*)d_out, 0);
}

// round 3
// speedup vs baseline: 1.5061x; 1.5061x over previous
#include <cuda_runtime.h>
#include <cstdint>

// ============================================================================
// ViTMAE attention block: B=16, S=1024, HID=1024, HEADS=16, D=64, fp32.
//   q/k/v = x@W + b (tf32 tensor-core GEMM, scatter to [B,H,S,D])
//   ctx   = softmax(q k^T / 8) v   (fused flash-style, fp32 SIMT)
//   out   = ctx@Wd + bd            (tf32 tensor-core GEMM)
// ============================================================================

#define BATCH   16
#define SEQ     1024
#define HID     1024
#define HEADS   16
#define HDIM    64
#define MROWS   (BATCH * SEQ)   // 16384

__device__ float g_q[(size_t)BATCH * HEADS * SEQ * HDIM];
__device__ float g_k[(size_t)BATCH * HEADS * SEQ * HDIM];
__device__ float g_v[(size_t)BATCH * HEADS * SEQ * HDIM];
__device__ float g_ctx[(size_t)MROWS * HID];

__device__ __forceinline__ float f2tf32(float x) {
    uint32_t u;
    asm("cvt.rna.tf32.f32 %0, %1;" : "=r"(u) : "f"(x));
    return __uint_as_float(u);
}

#define MMA_TF32(d, a, b)                                                     \
    asm volatile(                                                             \
        "mma.sync.aligned.m16n8k8.row.col.f32.tf32.tf32.f32 "                 \
        "{%0,%1,%2,%3}, {%4,%5,%6,%7}, {%8,%9}, {%0,%1,%2,%3};"               \
        : "+f"(d[0]), "+f"(d[1]), "+f"(d[2]), "+f"(d[3])                      \
        : "r"(a[0]), "r"(a[1]), "r"(a[2]), "r"(a[3]), "r"(b[0]), "r"(b[1]))

// ----------------------------------------------------------------------------
// tf32 tensor-core GEMM: C[M,N] = A[M,K] @ W[K,N] + bias[N]
// BM=128, BN=128, BK=16, 256 threads (8 warps, 2x4), warp tile 64x32.
// MODE 0: A = g_ctx, out = outArg row-major.
// MODE 1: A = Ain,   out = g_q/g_k/g_v per `which`, scattered to [B,H,S,D].
// ----------------------------------------------------------------------------
template <int MODE>
__global__ __launch_bounds__(256) void mma_gemm(
    const float* __restrict__ Ain, const float* __restrict__ W,
    const float* __restrict__ bias, float* __restrict__ outArg, int which)
{
    const int K = HID, N = HID;
    __shared__ float As[128][20];    // [m][k], pad->stride 20 (conflict-free frags)
    __shared__ float Bs[16][136];    // [k][n], pad->stride 136 (8 mod 32)

    const float* A = (MODE == 0) ? g_ctx : Ain;
    float* out;
    if (MODE == 0) out = outArg;
    else           out = (which == 0) ? g_q : (which == 1) ? g_k : g_v;

    const int tid = threadIdx.x;
    const int lane = tid & 31, warp = tid >> 5;
    const int wm = warp >> 2, wn = warp & 3;       // warps: 2 (m) x 4 (n)
    const int g = lane >> 2, t = lane & 3;         // fragment coords

    const int row0 = blockIdx.y * 128;
    const int col0 = blockIdx.x * 128;

    float acc[4][4][4];
#pragma unroll
    for (int mt = 0; mt < 4; mt++)
#pragma unroll
        for (int nt = 0; nt < 4; nt++)
#pragma unroll
            for (int i = 0; i < 4; i++) acc[mt][nt][i] = 0.f;

    for (int k0 = 0; k0 < K; k0 += 16) {
        // Stage A tile: 128 rows x 16 cols, tf32-convert on the way in.
        {
            int r = tid >> 1;
            int c = (tid & 1) * 8;
            float4 v0 = *(const float4*)&A[(size_t)(row0 + r) * K + k0 + c];
            float4 v1 = *(const float4*)&A[(size_t)(row0 + r) * K + k0 + c + 4];
            As[r][c + 0] = f2tf32(v0.x); As[r][c + 1] = f2tf32(v0.y);
            As[r][c + 2] = f2tf32(v0.z); As[r][c + 3] = f2tf32(v0.w);
            As[r][c + 4] = f2tf32(v1.x); As[r][c + 5] = f2tf32(v1.y);
            As[r][c + 6] = f2tf32(v1.z); As[r][c + 7] = f2tf32(v1.w);
        }
        // Stage B tile: 16 rows x 128 cols.
        {
            int r = tid >> 4;
            int c = (tid & 15) * 8;
            float4 v0 = *(const float4*)&W[(size_t)(k0 + r) * N + col0 + c];
            float4 v1 = *(const float4*)&W[(size_t)(k0 + r) * N + col0 + c + 4];
            Bs[r][c + 0] = f2tf32(v0.x); Bs[r][c + 1] = f2tf32(v0.y);
            Bs[r][c + 2] = f2tf32(v0.z); Bs[r][c + 3] = f2tf32(v0.w);
            Bs[r][c + 4] = f2tf32(v1.x); Bs[r][c + 5] = f2tf32(v1.y);
            Bs[r][c + 6] = f2tf32(v1.z); Bs[r][c + 7] = f2tf32(v1.w);
        }
        __syncthreads();

#pragma unroll
        for (int ks = 0; ks < 16; ks += 8) {
            uint32_t a[4][4], b[4][2];
#pragma unroll
            for (int mt = 0; mt < 4; mt++) {
                int m = wm * 64 + mt * 16;
                a[mt][0] = __float_as_uint(As[m + g    ][ks + t    ]);
                a[mt][1] = __float_as_uint(As[m + g + 8][ks + t    ]);
                a[mt][2] = __float_as_uint(As[m + g    ][ks + t + 4]);
                a[mt][3] = __float_as_uint(As[m + g + 8][ks + t + 4]);
            }
#pragma unroll
            for (int nt = 0; nt < 4; nt++) {
                int n = wn * 32 + nt * 8 + g;
                b[nt][0] = __float_as_uint(Bs[ks + t    ][n]);
                b[nt][1] = __float_as_uint(Bs[ks + t + 4][n]);
            }
#pragma unroll
            for (int mt = 0; mt < 4; mt++)
#pragma unroll
                for (int nt = 0; nt < 4; nt++)
                    MMA_TF32(acc[mt][nt], a[mt], b[nt]);
        }
        __syncthreads();
    }

    // Epilogue: c frag rows (g, g+8), cols (2t, 2t+1)
#pragma unroll
    for (int mt = 0; mt < 4; mt++) {
#pragma unroll
        for (int nt = 0; nt < 4; nt++) {
            int n = col0 + wn * 32 + nt * 8 + 2 * t;
            float b0 = bias[n], b1 = bias[n + 1];
#pragma unroll
            for (int half = 0; half < 2; half++) {
                int m = row0 + wm * 64 + mt * 16 + g + half * 8;
                float2 v;
                v.x = acc[mt][nt][half * 2 + 0] + b0;
                v.y = acc[mt][nt][half * 2 + 1] + b1;
                if (MODE == 0) {
                    *(float2*)&out[(size_t)m * N + n] = v;
                } else {
                    int bb = m >> 10, s = m & 1023;
                    int h = n >> 6, d = n & 63;    // even pair never crosses head
                    *(float2*)&out[(((size_t)bb * HEADS + h) * SEQ + s) * HDIM + d] = v;
                }
            }
        }
    }
}

// ----------------------------------------------------------------------------
// Fused attention (flash-style, online softmax), fp32 SIMT. Unchanged (known
// correct); tensor-core port is the next-round target.
// ----------------------------------------------------------------------------
__global__ __launch_bounds__(256) void attn_kernel()
{
    __shared__ float Qs[64][65];
    __shared__ float Ks[32][65];
    __shared__ float Vs[32][64];
    __shared__ float Ps[64][33];
    __shared__ float m_s[64], l_s[64], corr_s[64];

    const int tid = threadIdx.x;
    const int ty = tid / 16, tx = tid % 16;
    const int qt = blockIdx.x, h = blockIdx.y, b = blockIdx.z;
    const size_t bh = (size_t)b * HEADS + h;
    const float* __restrict__ qb = g_q + (bh * SEQ + qt * 64) * HDIM;
    const float* __restrict__ kb = g_k + bh * SEQ * HDIM;
    const float* __restrict__ vb = g_v + bh * SEQ * HDIM;

    for (int idx = tid; idx < 64 * 16; idx += 256) {
        int r = idx / 16, c4 = (idx % 16) * 4;
        float4 val = *(const float4*)&qb[r * HDIM + c4];
        Qs[r][c4 + 0] = val.x; Qs[r][c4 + 1] = val.y;
        Qs[r][c4 + 2] = val.z; Qs[r][c4 + 3] = val.w;
    }
    if (tid < 64) { m_s[tid] = -1e30f; l_s[tid] = 0.f; }

    float o[4][4];
#pragma unroll
    for (int i = 0; i < 4; i++)
#pragma unroll
        for (int j = 0; j < 4; j++) o[i][j] = 0.f;

    const float scale = 0.125f;
    __syncthreads();

    for (int kc = 0; kc < SEQ; kc += 32) {
        for (int idx = tid; idx < 32 * 16; idx += 256) {
            int r = idx / 16, c4 = (idx % 16) * 4;
            float4 kv = *(const float4*)&kb[(size_t)(kc + r) * HDIM + c4];
            Ks[r][c4 + 0] = kv.x; Ks[r][c4 + 1] = kv.y;
            Ks[r][c4 + 2] = kv.z; Ks[r][c4 + 3] = kv.w;
            float4 vv = *(const float4*)&vb[(size_t)(kc + r) * HDIM + c4];
            *(float4*)&Vs[r][c4] = vv;
        }
        __syncthreads();

        {
            float sc[4][2];
#pragma unroll
            for (int i = 0; i < 4; i++) { sc[i][0] = 0.f; sc[i][1] = 0.f; }
#pragma unroll
            for (int kk = 0; kk < 64; kk++) {
                float a0 = Qs[ty * 4 + 0][kk];
                float a1 = Qs[ty * 4 + 1][kk];
                float a2 = Qs[ty * 4 + 2][kk];
                float a3 = Qs[ty * 4 + 3][kk];
                float b0 = Ks[tx * 2 + 0][kk];
                float b1 = Ks[tx * 2 + 1][kk];
                sc[0][0] += a0 * b0; sc[0][1] += a0 * b1;
                sc[1][0] += a1 * b0; sc[1][1] += a1 * b1;
                sc[2][0] += a2 * b0; sc[2][1] += a2 * b1;
                sc[3][0] += a3 * b0; sc[3][1] += a3 * b1;
            }
#pragma unroll
            for (int i = 0; i < 4; i++) {
                Ps[ty * 4 + i][tx * 2 + 0] = sc[i][0] * scale;
                Ps[ty * 4 + i][tx * 2 + 1] = sc[i][1] * scale;
            }
        }
        __syncthreads();

        if (tid < 64) {
            float m_old = m_s[tid];
            float mx = m_old;
#pragma unroll
            for (int c = 0; c < 32; c++) mx = fmaxf(mx, Ps[tid][c]);
            float corr = __expf(m_old - mx);
            float sum = 0.f;
#pragma unroll
            for (int c = 0; c < 32; c++) {
                float e = __expf(Ps[tid][c] - mx);
                Ps[tid][c] = e;
                sum += e;
            }
            m_s[tid] = mx;
            l_s[tid] = l_s[tid] * corr + sum;
            corr_s[tid] = corr;
        }
        __syncthreads();

        {
            float c0 = corr_s[ty * 4 + 0];
            float c1 = corr_s[ty * 4 + 1];
            float c2 = corr_s[ty * 4 + 2];
            float c3 = corr_s[ty * 4 + 3];
#pragma unroll
            for (int j = 0; j < 4; j++) {
                o[0][j] *= c0; o[1][j] *= c1; o[2][j] *= c2; o[3][j] *= c3;
            }
#pragma unroll
            for (int c = 0; c < 32; c++) {
                float p0 = Ps[ty * 4 + 0][c];
                float p1 = Ps[ty * 4 + 1][c];
                float p2 = Ps[ty * 4 + 2][c];
                float p3 = Ps[ty * 4 + 3][c];
                float4 vv = *(const float4*)&Vs[c][tx * 4];
                o[0][0] += p0 * vv.x; o[0][1] += p0 * vv.y; o[0][2] += p0 * vv.z; o[0][3] += p0 * vv.w;
                o[1][0] += p1 * vv.x; o[1][1] += p1 * vv.y; o[1][2] += p1 * vv.z; o[1][3] += p1 * vv.w;
                o[2][0] += p2 * vv.x; o[2][1] += p2 * vv.y; o[2][2] += p2 * vv.z; o[2][3] += p2 * vv.w;
                o[3][0] += p3 * vv.x; o[3][1] += p3 * vv.y; o[3][2] += p3 * vv.z; o[3][3] += p3 * vv.w;
            }
        }
        __syncthreads();
    }

    if (tid < 64) corr_s[tid] = 1.f / l_s[tid];
    __syncthreads();

#pragma unroll
    for (int i = 0; i < 4; i++) {
        int r = ty * 4 + i;
        float inv = corr_s[r];
        float4 w;
        w.x = o[i][0] * inv; w.y = o[i][1] * inv;
        w.z = o[i][2] * inv; w.w = o[i][3] * inv;
        size_t off = ((size_t)b * SEQ + qt * 64 + r) * HID + h * HDIM + tx * 4;
        *(float4*)&g_ctx[off] = w;
    }
}

// ----------------------------------------------------------------------------
extern "C" void kernel_launch(void* const* d_in, const int* in_sizes, int n_in,
                              void* d_out, int out_size)
{
    const float* hs = (const float*)d_in[0];
    const float* Wq = (const float*)d_in[1];
    const float* bq = (const float*)d_in[2];
    const float* Wk = (const float*)d_in[3];
    const float* bk = (const float*)d_in[4];
    const float* Wv = (const float*)d_in[5];
    const float* bv = (const float*)d_in[6];
    const float* Wd = (const float*)d_in[7];
    const float* bd = (const float*)d_in[8];

    dim3 gemmGrid(HID / 128, MROWS / 128);   // (8, 128)
    mma_gemm<1><<<gemmGrid, 256>>>(hs, Wq, bq, nullptr, 0);
    mma_gemm<1><<<gemmGrid, 256>>>(hs, Wk, bk, nullptr, 1);
    mma_gemm<1><<<gemmGrid, 256>>>(hs, Wv, bv, nullptr, 2);

    attn_kernel<<<dim3(SEQ / 64, HEADS, BATCH), 256>>>();

    mma_gemm<0><<<gemmGrid, 256>>>(nullptr, Wd, bd, (float*)d_out, 0);
}

// round 4
// speedup vs baseline: 2.9593x; 1.9650x over previous
#include <cuda_runtime.h>
#include <cstdint>

// ============================================================================
// ViTMAE attention block: B=16, S=1024, HID=1024, HEADS=16, D=64, fp32.
// All GEMM-shaped work on tf32 tensor cores (mma.m16n8k8).
//   pre-round: x, Wq/k/v/d  -> tf32 copies (one cheap pass)
//   q/k/v = x@W + b   (cp.async double-buffered tf32 MMA, scatter [B,H,S,D])
//   ctx   = softmax(q k^T / 8) v   (tensor-core flash attention)
//   out   = ctx@Wd + bd
// ============================================================================

#define BATCH   16
#define SEQ     1024
#define HID     1024
#define HEADS   16
#define HDIM    64
#define MROWS   (BATCH * SEQ)   // 16384

__device__ float g_q[(size_t)BATCH * HEADS * SEQ * HDIM];
__device__ float g_k[(size_t)BATCH * HEADS * SEQ * HDIM];
__device__ float g_v[(size_t)BATCH * HEADS * SEQ * HDIM];
__device__ float g_ctx[(size_t)MROWS * HID];
__device__ float g_hs[(size_t)MROWS * HID];
__device__ float g_wq[(size_t)HID * HID];
__device__ float g_wk[(size_t)HID * HID];
__device__ float g_wv[(size_t)HID * HID];
__device__ float g_wd[(size_t)HID * HID];

__device__ __forceinline__ float f2tf32(float x) {
    uint32_t u;
    asm("cvt.rna.tf32.f32 %0, %1;" : "=r"(u) : "f"(x));
    return __uint_as_float(u);
}

__device__ __forceinline__ void cp16(void* smem, const void* gmem) {
    uint32_t s = (uint32_t)__cvta_generic_to_shared(smem);
    asm volatile("cp.async.cg.shared.global [%0], [%1], 16;" :: "r"(s), "l"(gmem));
}

#define MMA_TF32(d, a, b)                                                     \
    asm volatile(                                                             \
        "mma.sync.aligned.m16n8k8.row.col.f32.tf32.tf32.f32 "                 \
        "{%0,%1,%2,%3}, {%4,%5,%6,%7}, {%8,%9}, {%0,%1,%2,%3};"               \
        : "+f"(d[0]), "+f"(d[1]), "+f"(d[2]), "+f"(d[3])                      \
        : "r"(a[0]), "r"(a[1]), "r"(a[2]), "r"(a[3]), "r"(b[0]), "r"(b[1]))

// ----------------------------------------------------------------------------
// tf32 pre-round pass: dst[i] = tf32(src[i]). which: 0=hs 1=Wq 2=Wk 3=Wv 4=Wd
// ----------------------------------------------------------------------------
__global__ __launch_bounds__(256) void round_copy(const float* __restrict__ src,
                                                  int which, int n4)
{
    float* dst = which == 0 ? g_hs : which == 1 ? g_wq :
                 which == 2 ? g_wk : which == 3 ? g_wv : g_wd;
    int i = blockIdx.x * blockDim.x + threadIdx.x;
    if (i < n4) {
        float4 v = ((const float4*)src)[i];
        v.x = f2tf32(v.x); v.y = f2tf32(v.y);
        v.z = f2tf32(v.z); v.w = f2tf32(v.w);
        ((float4*)dst)[i] = v;
    }
}

// ----------------------------------------------------------------------------
// tf32 GEMM, cp.async 2-stage pipeline: C[M,N] = A[M,K] @ W[K,N] + bias
// BM=128, BN=128, BK=16, 256 threads (8 warps 2x4), warp tile 64x32.
// MODE 0: A=g_ctx (tf32-rounded by attn), W=g_wd, out=outArg row-major.
// MODE 1: A=g_hs, W per which, out scattered to [B,H,S,D] into g_q/g_k/g_v.
// ----------------------------------------------------------------------------
template <int MODE>
__global__ __launch_bounds__(256) void mma_gemm(
    const float* __restrict__ bias, float* __restrict__ outArg, int which)
{
    const int K = HID, N = HID;
    __shared__ float As[2][128][20];
    __shared__ float Bs[2][16][136];

    const float* __restrict__ A = (MODE == 0) ? g_ctx : g_hs;
    const float* __restrict__ W = which == 0 ? g_wq : which == 1 ? g_wk :
                                  which == 2 ? g_wv : g_wd;
    float* out;
    if (MODE == 0) out = outArg;
    else           out = (which == 0) ? g_q : (which == 1) ? g_k : g_v;

    const int tid = threadIdx.x;
    const int lane = tid & 31, warp = tid >> 5;
    const int wm = warp >> 2, wn = warp & 3;
    const int g = lane >> 2, t = lane & 3;
    const int row0 = blockIdx.y * 128;
    const int col0 = blockIdx.x * 128;

    float acc[4][4][4];
#pragma unroll
    for (int mt = 0; mt < 4; mt++)
#pragma unroll
        for (int nt = 0; nt < 4; nt++)
#pragma unroll
            for (int i = 0; i < 4; i++) acc[mt][nt][i] = 0.f;

    auto stage = [&](int buf, int k0) {
#pragma unroll
        for (int j = 0; j < 2; j++) {
            int cid = tid + j * 256;
            int ar = cid >> 2, ac = (cid & 3) * 4;
            cp16(&As[buf][ar][ac], &A[(size_t)(row0 + ar) * K + k0 + ac]);
            int br = cid >> 5, bc = (cid & 31) * 4;
            cp16(&Bs[buf][br][bc], &W[(size_t)(k0 + br) * N + col0 + bc]);
        }
    };

    stage(0, 0);
    asm volatile("cp.async.commit_group;");

    const int NIT = K / 16;
    for (int it = 0; it < NIT; it++) {
        if (it + 1 < NIT) {
            stage((it + 1) & 1, (it + 1) * 16);
            asm volatile("cp.async.commit_group;");
            asm volatile("cp.async.wait_group 1;");
        } else {
            asm volatile("cp.async.wait_group 0;");
        }
        __syncthreads();

        int buf = it & 1;
#pragma unroll
        for (int ks = 0; ks < 16; ks += 8) {
            uint32_t a[4][4], b[4][2];
#pragma unroll
            for (int mt = 0; mt < 4; mt++) {
                int m = wm * 64 + mt * 16;
                a[mt][0] = __float_as_uint(As[buf][m + g    ][ks + t    ]);
                a[mt][1] = __float_as_uint(As[buf][m + g + 8][ks + t    ]);
                a[mt][2] = __float_as_uint(As[buf][m + g    ][ks + t + 4]);
                a[mt][3] = __float_as_uint(As[buf][m + g + 8][ks + t + 4]);
            }
#pragma unroll
            for (int nt = 0; nt < 4; nt++) {
                int n = wn * 32 + nt * 8 + g;
                b[nt][0] = __float_as_uint(Bs[buf][ks + t    ][n]);
                b[nt][1] = __float_as_uint(Bs[buf][ks + t + 4][n]);
            }
#pragma unroll
            for (int mt = 0; mt < 4; mt++)
#pragma unroll
                for (int nt = 0; nt < 4; nt++)
                    MMA_TF32(acc[mt][nt], a[mt], b[nt]);
        }
        __syncthreads();
    }

#pragma unroll
    for (int mt = 0; mt < 4; mt++) {
#pragma unroll
        for (int nt = 0; nt < 4; nt++) {
            int n = col0 + wn * 32 + nt * 8 + 2 * t;
            float b0 = bias[n], b1 = bias[n + 1];
#pragma unroll
            for (int half = 0; half < 2; half++) {
                int m = row0 + wm * 64 + mt * 16 + g + half * 8;
                float2 v;
                v.x = acc[mt][nt][half * 2 + 0] + b0;
                v.y = acc[mt][nt][half * 2 + 1] + b1;
                if (MODE == 0) {
                    *(float2*)&out[(size_t)m * N + n] = v;
                } else {
                    int bb = m >> 10, s = m & 1023;
                    int h = n >> 6, d = n & 63;
                    *(float2*)&out[(((size_t)bb * HEADS + h) * SEQ + s) * HDIM + d] = v;
                }
            }
        }
    }
}

// ----------------------------------------------------------------------------
// Tensor-core flash attention. Grid (16 qtiles, 16 h, 16 b), 128 threads.
// Br=64 (16 rows per warp), Bc=32, D=64. tf32 mma for QK^T and PV,
// register-resident online softmax (exp2, quad shuffles).
// Writes ctx tf32-rounded (consumed by MODE-0 GEMM without cvt).
// ----------------------------------------------------------------------------
__global__ __launch_bounds__(128) void attn_kernel()
{
    __shared__ float Qs[64][68];   // banks (4g+t): conflict-free frag reads
    __shared__ float Ks[32][68];
    __shared__ float Vs[32][72];   // banks (8t+g): conflict-free frag reads
    __shared__ float Ps[64][36];

    const int tid = threadIdx.x;
    const int lane = tid & 31, warp = tid >> 5;
    const int g = lane >> 2, t = lane & 3;
    const int w16 = warp * 16;
    const int qt = blockIdx.x, h = blockIdx.y, b = blockIdx.z;
    const size_t bh = (size_t)b * HEADS + h;
    const float* __restrict__ qb = g_q + (bh * SEQ + qt * 64) * HDIM;
    const float* __restrict__ kb = g_k + bh * SEQ * HDIM;
    const float* __restrict__ vb = g_v + bh * SEQ * HDIM;

    // Q staged once, scaled by (1/sqrt(D)) * log2(e) so softmax uses exp2
    const float qscale = 0.125f * 1.44269504088896f;
    for (int idx = tid; idx < 64 * 16; idx += 128) {
        int r = idx >> 4, c = (idx & 15) * 4;
        float4 v = *(const float4*)&qb[(size_t)r * HDIM + c];
        Qs[r][c + 0] = f2tf32(v.x * qscale);
        Qs[r][c + 1] = f2tf32(v.y * qscale);
        Qs[r][c + 2] = f2tf32(v.z * qscale);
        Qs[r][c + 3] = f2tf32(v.w * qscale);
    }

    float m0 = -1e30f, m1 = -1e30f, l0 = 0.f, l1 = 0.f;
    float o[8][4];
#pragma unroll
    for (int d = 0; d < 8; d++)
#pragma unroll
        for (int i = 0; i < 4; i++) o[d][i] = 0.f;

    __syncthreads();

    for (int kc = 0; kc < SEQ; kc += 32) {
        // stage K,V tiles (32x64 each)
        for (int idx = tid; idx < 32 * 16; idx += 128) {
            int r = idx >> 4, c = (idx & 15) * 4;
            float4 kv = *(const float4*)&kb[(size_t)(kc + r) * HDIM + c];
            Ks[r][c + 0] = f2tf32(kv.x); Ks[r][c + 1] = f2tf32(kv.y);
            Ks[r][c + 2] = f2tf32(kv.z); Ks[r][c + 3] = f2tf32(kv.w);
            float4 vv = *(const float4*)&vb[(size_t)(kc + r) * HDIM + c];
            Vs[r][c + 0] = f2tf32(vv.x); Vs[r][c + 1] = f2tf32(vv.y);
            Vs[r][c + 2] = f2tf32(vv.z); Vs[r][c + 3] = f2tf32(vv.w);
        }
        __syncthreads();

        // S[16x32] = Q_warp @ K^T  (m=q rows, n=k rows, k=d)
        float sc[4][4];
#pragma unroll
        for (int nt = 0; nt < 4; nt++)
#pragma unroll
            for (int i = 0; i < 4; i++) sc[nt][i] = 0.f;

#pragma unroll
        for (int ks = 0; ks < 64; ks += 8) {
            uint32_t a[4];
            a[0] = __float_as_uint(Qs[w16 + g    ][ks + t    ]);
            a[1] = __float_as_uint(Qs[w16 + g + 8][ks + t    ]);
            a[2] = __float_as_uint(Qs[w16 + g    ][ks + t + 4]);
            a[3] = __float_as_uint(Qs[w16 + g + 8][ks + t + 4]);
#pragma unroll
            for (int nt = 0; nt < 4; nt++) {
                uint32_t bfr[2];
                bfr[0] = __float_as_uint(Ks[nt * 8 + g][ks + t    ]);
                bfr[1] = __float_as_uint(Ks[nt * 8 + g][ks + t + 4]);
                MMA_TF32(sc[nt], a, bfr);
            }
        }

        // online softmax in registers (rows g and g+8)
        float mx0 = -1e30f, mx1 = -1e30f;
#pragma unroll
        for (int nt = 0; nt < 4; nt++) {
            mx0 = fmaxf(mx0, fmaxf(sc[nt][0], sc[nt][1]));
            mx1 = fmaxf(mx1, fmaxf(sc[nt][2], sc[nt][3]));
        }
        mx0 = fmaxf(mx0, __shfl_xor_sync(0xffffffffu, mx0, 1));
        mx0 = fmaxf(mx0, __shfl_xor_sync(0xffffffffu, mx0, 2));
        mx1 = fmaxf(mx1, __shfl_xor_sync(0xffffffffu, mx1, 1));
        mx1 = fmaxf(mx1, __shfl_xor_sync(0xffffffffu, mx1, 2));

        float mn0 = fmaxf(m0, mx0), mn1 = fmaxf(m1, mx1);
        float corr0 = exp2f(m0 - mn0), corr1 = exp2f(m1 - mn1);
        m0 = mn0; m1 = mn1;

        float sum0 = 0.f, sum1 = 0.f;
#pragma unroll
        for (int nt = 0; nt < 4; nt++) {
            float p00 = exp2f(sc[nt][0] - mn0);
            float p01 = exp2f(sc[nt][1] - mn0);
            float p10 = exp2f(sc[nt][2] - mn1);
            float p11 = exp2f(sc[nt][3] - mn1);
            sum0 += p00 + p01;
            sum1 += p10 + p11;
            float2 w0 = make_float2(f2tf32(p00), f2tf32(p01));
            float2 w1 = make_float2(f2tf32(p10), f2tf32(p11));
            *(float2*)&Ps[w16 + g    ][nt * 8 + 2 * t] = w0;
            *(float2*)&Ps[w16 + g + 8][nt * 8 + 2 * t] = w1;
        }
        sum0 += __shfl_xor_sync(0xffffffffu, sum0, 1);
        sum0 += __shfl_xor_sync(0xffffffffu, sum0, 2);
        sum1 += __shfl_xor_sync(0xffffffffu, sum1, 1);
        sum1 += __shfl_xor_sync(0xffffffffu, sum1, 2);
        l0 = l0 * corr0 + sum0;
        l1 = l1 * corr1 + sum1;

#pragma unroll
        for (int d = 0; d < 8; d++) {
            o[d][0] *= corr0; o[d][1] *= corr0;
            o[d][2] *= corr1; o[d][3] *= corr1;
        }
        __syncwarp();

        // O[16x64] += P[16x32] @ V[32x64]
#pragma unroll
        for (int kk = 0; kk < 32; kk += 8) {
            uint32_t a[4];
            a[0] = __float_as_uint(Ps[w16 + g    ][kk + t    ]);
            a[1] = __float_as_uint(Ps[w16 + g + 8][kk + t    ]);
            a[2] = __float_as_uint(Ps[w16 + g    ][kk + t + 4]);
            a[3] = __float_as_uint(Ps[w16 + g + 8][kk + t + 4]);
#pragma unroll
            for (int d = 0; d < 8; d++) {
                uint32_t bfr[2];
                bfr[0] = __float_as_uint(Vs[kk + t    ][d * 8 + g]);
                bfr[1] = __float_as_uint(Vs[kk + t + 4][d * 8 + g]);
                MMA_TF32(o[d], a, bfr);
            }
        }
        __syncthreads();   // done with Ks/Vs before next staging
    }

    float inv0 = 1.f / l0, inv1 = 1.f / l1;
    const int r0 = qt * 64 + w16 + g;
#pragma unroll
    for (int d = 0; d < 8; d++) {
        int col = h * HDIM + d * 8 + 2 * t;
        float2 w0 = make_float2(f2tf32(o[d][0] * inv0), f2tf32(o[d][1] * inv0));
        float2 w1 = make_float2(f2tf32(o[d][2] * inv1), f2tf32(o[d][3] * inv1));
        *(float2*)&g_ctx[((size_t)b * SEQ + r0    ) * HID + col] = w0;
        *(float2*)&g_ctx[((size_t)b * SEQ + r0 + 8) * HID + col] = w1;
    }
}

// ----------------------------------------------------------------------------
extern "C" void kernel_launch(void* const* d_in, const int* in_sizes, int n_in,
                              void* d_out, int out_size)
{
    const float* hs = (const float*)d_in[0];
    const float* Wq = (const float*)d_in[1];
    const float* bq = (const float*)d_in[2];
    const float* Wk = (const float*)d_in[3];
    const float* bk = (const float*)d_in[4];
    const float* Wv = (const float*)d_in[5];
    const float* bv = (const float*)d_in[6];
    const float* Wd = (const float*)d_in[7];
    const float* bd = (const float*)d_in[8];

    const int n4_hs = MROWS * HID / 4;       // 4194304
    const int n4_w  = HID * HID / 4;         // 262144
    round_copy<<<(n4_hs + 255) / 256, 256>>>(hs, 0, n4_hs);
    round_copy<<<(n4_w  + 255) / 256, 256>>>(Wq, 1, n4_w);
    round_copy<<<(n4_w  + 255) / 256, 256>>>(Wk, 2, n4_w);
    round_copy<<<(n4_w  + 255) / 256, 256>>>(Wv, 3, n4_w);
    round_copy<<<(n4_w  + 255) / 256, 256>>>(Wd, 4, n4_w);

    dim3 gemmGrid(HID / 128, MROWS / 128);   // (8, 128)
    mma_gemm<1><<<gemmGrid, 256>>>(bq, nullptr, 0);
    mma_gemm<1><<<gemmGrid, 256>>>(bk, nullptr, 1);
    mma_gemm<1><<<gemmGrid, 256>>>(bv, nullptr, 2);

    attn_kernel<<<dim3(SEQ / 64, HEADS, BATCH), 128>>>();

    mma_gemm<0><<<gemmGrid, 256>>>(bd, (float*)d_out, 3);
}

// round 5
// speedup vs baseline: 3.2099x; 1.0847x over previous
#include <cuda_runtime.h>
#include <cstdint>

// ============================================================================
// ViTMAE attention block: B=16, S=1024, HID=1024, HEADS=16, D=64, fp32.
// tf32 tensor cores everywhere (mma.m16n8k8):
//   pre-round: x, W* -> tf32
//   q/k/v = x@W + b   (3-stage cp.async tf32 MMA; epilogue rounds to tf32,
//                      q additionally scaled by 0.125*log2e; scatter [B,H,S,D])
//   ctx   = softmax(q k^T) v  (cp.async 3-stage tensor-core flash attention)
//   out   = ctx@Wd + bd
// ============================================================================

#define BATCH   16
#define SEQ     1024
#define HID     1024
#define HEADS   16
#define HDIM    64
#define MROWS   (BATCH * SEQ)   // 16384

__device__ float g_q[(size_t)BATCH * HEADS * SEQ * HDIM];
__device__ float g_k[(size_t)BATCH * HEADS * SEQ * HDIM];
__device__ float g_v[(size_t)BATCH * HEADS * SEQ * HDIM];
__device__ float g_ctx[(size_t)MROWS * HID];
__device__ float g_hs[(size_t)MROWS * HID];
__device__ float g_wq[(size_t)HID * HID];
__device__ float g_wk[(size_t)HID * HID];
__device__ float g_wv[(size_t)HID * HID];
__device__ float g_wd[(size_t)HID * HID];

__device__ __forceinline__ float f2tf32(float x) {
    uint32_t u;
    asm("cvt.rna.tf32.f32 %0, %1;" : "=r"(u) : "f"(x));
    return __uint_as_float(u);
}

__device__ __forceinline__ void cp16(void* smem, const void* gmem) {
    uint32_t s = (uint32_t)__cvta_generic_to_shared(smem);
    asm volatile("cp.async.cg.shared.global [%0], [%1], 16;" :: "r"(s), "l"(gmem));
}
#define CP_COMMIT() asm volatile("cp.async.commit_group;")
#define CP_WAIT(n)  asm volatile("cp.async.wait_group %0;" :: "n"(n))

#define MMA_TF32(d, a, b)                                                     \
    asm volatile(                                                             \
        "mma.sync.aligned.m16n8k8.row.col.f32.tf32.tf32.f32 "                 \
        "{%0,%1,%2,%3}, {%4,%5,%6,%7}, {%8,%9}, {%0,%1,%2,%3};"               \
        : "+f"(d[0]), "+f"(d[1]), "+f"(d[2]), "+f"(d[3])                      \
        : "r"(a[0]), "r"(a[1]), "r"(a[2]), "r"(a[3]), "r"(b[0]), "r"(b[1]))

// ----------------------------------------------------------------------------
// tf32 pre-round pass. which: 0=hs 1=Wq 2=Wk 3=Wv 4=Wd
// ----------------------------------------------------------------------------
__global__ __launch_bounds__(256) void round_copy(const float* __restrict__ src,
                                                  int which, int n4)
{
    float* dst = which == 0 ? g_hs : which == 1 ? g_wq :
                 which == 2 ? g_wk : which == 3 ? g_wv : g_wd;
    int i = blockIdx.x * blockDim.x + threadIdx.x;
    if (i < n4) {
        float4 v = ((const float4*)src)[i];
        v.x = f2tf32(v.x); v.y = f2tf32(v.y);
        v.z = f2tf32(v.z); v.w = f2tf32(v.w);
        ((float4*)dst)[i] = v;
    }
}

// ----------------------------------------------------------------------------
// tf32 GEMM, 3-stage cp.async, ONE __syncthreads per K-iter.
// BM=128, BN=128, BK=16, 256 threads (8 warps 2x4), warp tile 64x32.
// MODE 0: A=g_ctx, W=g_wd, out=outArg row-major fp32 (+bias).
// MODE 1: A=g_hs, W per which, out=(q|k|v) scattered [B,H,S,D],
//         value = tf32_round((acc+bias)*osc).
// Dynamic smem: 3*(128*20 + 16*136)*4 = 56832 B.
// ----------------------------------------------------------------------------
#define GEMM_SMEM ((3 * 128 * 20 + 3 * 16 * 136) * 4)

template <int MODE>
__global__ __launch_bounds__(256) void mma_gemm(
    const float* __restrict__ bias, float* __restrict__ outArg, int which,
    float osc)
{
    const int K = HID, N = HID;
    extern __shared__ float sm[];
    float* Asm = sm;                   // [3][128][20]
    float* Bsm = sm + 3 * 128 * 20;    // [3][16][136]
#define AS(s, r, c) Asm[(s) * 2560 + (r) * 20 + (c)]
#define BS(s, r, c) Bsm[(s) * 2176 + (r) * 136 + (c)]

    const float* __restrict__ A = (MODE == 0) ? g_ctx : g_hs;
    const float* __restrict__ W = which == 0 ? g_wq : which == 1 ? g_wk :
                                  which == 2 ? g_wv : g_wd;
    float* out;
    if (MODE == 0) out = outArg;
    else           out = (which == 0) ? g_q : (which == 1) ? g_k : g_v;

    const int tid = threadIdx.x;
    const int lane = tid & 31, warp = tid >> 5;
    const int wm = warp >> 2, wn = warp & 3;
    const int g = lane >> 2, t = lane & 3;
    const int row0 = blockIdx.y * 128;
    const int col0 = blockIdx.x * 128;

    float acc[4][4][4];
#pragma unroll
    for (int mt = 0; mt < 4; mt++)
#pragma unroll
        for (int nt = 0; nt < 4; nt++)
#pragma unroll
            for (int i = 0; i < 4; i++) acc[mt][nt][i] = 0.f;

    auto stage = [&](int s, int k0) {
#pragma unroll
        for (int j = 0; j < 2; j++) {
            int cid = tid + j * 256;
            int ar = cid >> 2, ac = (cid & 3) * 4;
            cp16(&AS(s, ar, ac), &A[(size_t)(row0 + ar) * K + k0 + ac]);
            int br = cid >> 5, bc = (cid & 31) * 4;
            cp16(&BS(s, br, bc), &W[(size_t)(k0 + br) * N + col0 + bc]);
        }
    };

    const int NIT = K / 16;   // 64
    stage(0, 0);  CP_COMMIT();
    stage(1, 16); CP_COMMIT();

    for (int it = 0; it < NIT; it++) {
        if (it + 1 < NIT) { CP_WAIT(1); } else { CP_WAIT(0); }
        __syncthreads();
        if (it + 2 < NIT) { stage((it + 2) % 3, (it + 2) * 16); CP_COMMIT(); }

        const int s = it % 3;
#pragma unroll
        for (int ks = 0; ks < 16; ks += 8) {
            uint32_t a[4][4], b[4][2];
#pragma unroll
            for (int mt = 0; mt < 4; mt++) {
                int m = wm * 64 + mt * 16;
                a[mt][0] = __float_as_uint(AS(s, m + g,     ks + t));
                a[mt][1] = __float_as_uint(AS(s, m + g + 8, ks + t));
                a[mt][2] = __float_as_uint(AS(s, m + g,     ks + t + 4));
                a[mt][3] = __float_as_uint(AS(s, m + g + 8, ks + t + 4));
            }
#pragma unroll
            for (int nt = 0; nt < 4; nt++) {
                int n = wn * 32 + nt * 8 + g;
                b[nt][0] = __float_as_uint(BS(s, ks + t,     n));
                b[nt][1] = __float_as_uint(BS(s, ks + t + 4, n));
            }
#pragma unroll
            for (int mt = 0; mt < 4; mt++)
#pragma unroll
                for (int nt = 0; nt < 4; nt++)
                    MMA_TF32(acc[mt][nt], a[mt], b[nt]);
        }
    }

#pragma unroll
    for (int mt = 0; mt < 4; mt++) {
#pragma unroll
        for (int nt = 0; nt < 4; nt++) {
            int n = col0 + wn * 32 + nt * 8 + 2 * t;
            float b0 = bias[n], b1 = bias[n + 1];
#pragma unroll
            for (int half = 0; half < 2; half++) {
                int m = row0 + wm * 64 + mt * 16 + g + half * 8;
                float2 v;
                v.x = acc[mt][nt][half * 2 + 0] + b0;
                v.y = acc[mt][nt][half * 2 + 1] + b1;
                if (MODE == 0) {
                    *(float2*)&out[(size_t)m * N + n] = v;
                } else {
                    v.x = f2tf32(v.x * osc);
                    v.y = f2tf32(v.y * osc);
                    int bb = m >> 10, ssq = m & 1023;
                    int h = n >> 6, d = n & 63;
                    *(float2*)&out[(((size_t)bb * HEADS + h) * SEQ + ssq) * HDIM + d] = v;
                }
            }
        }
    }
#undef AS
#undef BS
}

// ----------------------------------------------------------------------------
// Tensor-core flash attention, cp.async 3-stage K/V pipeline.
// Grid (8 qtiles, 16 h, 16 b), 256 threads (8 warps, 16 q-rows each).
// Br=128, Bc=32, D=64. Inputs pre-rounded tf32 (q pre-scaled by 0.125*log2e).
// Dynamic smem: Q 128x68 | K 3x32x68 | V 3x32x72 | P 128x36 = 107008 B.
// ----------------------------------------------------------------------------
#define ATTN_SMEM ((128 * 68 + 3 * 32 * 68 + 3 * 32 * 72 + 128 * 36) * 4)

__global__ __launch_bounds__(256) void attn_kernel()
{
    extern __shared__ float sm[];
#define QS(r, c)    sm[(r) * 68 + (c)]
#define KS(s, r, c) sm[8704 + (s) * 2176 + (r) * 68 + (c)]
#define VS(s, r, c) sm[15232 + (s) * 2304 + (r) * 72 + (c)]
#define PS(r, c)    sm[22144 + (r) * 36 + (c)]

    const int tid = threadIdx.x;
    const int lane = tid & 31, warp = tid >> 5;
    const int g = lane >> 2, t = lane & 3;
    const int w16 = warp * 16;
    const int qt = blockIdx.x, h = blockIdx.y, b = blockIdx.z;
    const size_t bh = (size_t)b * HEADS + h;
    const float* __restrict__ qb = g_q + (bh * SEQ + qt * 128) * HDIM;
    const float* __restrict__ kb = g_k + bh * SEQ * HDIM;
    const float* __restrict__ vb = g_v + bh * SEQ * HDIM;

    auto stageKV = [&](int s, int kc) {
#pragma unroll
        for (int j = 0; j < 2; j++) {
            int i = tid + j * 256;                 // 512 chunks each
            int r = i >> 4, c4 = (i & 15) * 4;
            cp16(&KS(s, r, c4), &kb[(size_t)(kc + r) * HDIM + c4]);
            cp16(&VS(s, r, c4), &vb[(size_t)(kc + r) * HDIM + c4]);
        }
    };

    // Q: 128x64 = 2048 16B chunks
#pragma unroll
    for (int j = 0; j < 8; j++) {
        int i = tid + j * 256;
        int r = i >> 4, c4 = (i & 15) * 4;
        cp16(&QS(r, c4), &qb[(size_t)r * HDIM + c4]);
    }
    stageKV(0, 0);  CP_COMMIT();     // group 0 = Q + KV0
    stageKV(1, 32); CP_COMMIT();     // group 1 = KV1

    float m0 = -1e30f, m1 = -1e30f, l0 = 0.f, l1 = 0.f;
    float o[8][4];
#pragma unroll
    for (int d = 0; d < 8; d++)
#pragma unroll
        for (int i = 0; i < 4; i++) o[d][i] = 0.f;

    const int NKV = SEQ / 32;   // 32
    for (int it = 0; it < NKV; it++) {
        if (it + 1 < NKV) { CP_WAIT(1); } else { CP_WAIT(0); }
        __syncthreads();
        if (it + 2 < NKV) { stageKV((it + 2) % 3, (it + 2) * 32); CP_COMMIT(); }

        const int s = it % 3;

        // S[16x32] = Q_warp @ K^T
        float sc[4][4];
#pragma unroll
        for (int nt = 0; nt < 4; nt++)
#pragma unroll
            for (int i = 0; i < 4; i++) sc[nt][i] = 0.f;

#pragma unroll
        for (int ks = 0; ks < 64; ks += 8) {
            uint32_t a[4];
            a[0] = __float_as_uint(QS(w16 + g,     ks + t));
            a[1] = __float_as_uint(QS(w16 + g + 8, ks + t));
            a[2] = __float_as_uint(QS(w16 + g,     ks + t + 4));
            a[3] = __float_as_uint(QS(w16 + g + 8, ks + t + 4));
#pragma unroll
            for (int nt = 0; nt < 4; nt++) {
                uint32_t bf[2];
                bf[0] = __float_as_uint(KS(s, nt * 8 + g, ks + t));
                bf[1] = __float_as_uint(KS(s, nt * 8 + g, ks + t + 4));
                MMA_TF32(sc[nt], a, bf);
            }
        }

        // online softmax in registers (rows g, g+8 of warp tile)
        float mx0 = -1e30f, mx1 = -1e30f;
#pragma unroll
        for (int nt = 0; nt < 4; nt++) {
            mx0 = fmaxf(mx0, fmaxf(sc[nt][0], sc[nt][1]));
            mx1 = fmaxf(mx1, fmaxf(sc[nt][2], sc[nt][3]));
        }
        mx0 = fmaxf(mx0, __shfl_xor_sync(0xffffffffu, mx0, 1));
        mx0 = fmaxf(mx0, __shfl_xor_sync(0xffffffffu, mx0, 2));
        mx1 = fmaxf(mx1, __shfl_xor_sync(0xffffffffu, mx1, 1));
        mx1 = fmaxf(mx1, __shfl_xor_sync(0xffffffffu, mx1, 2));

        float mn0 = fmaxf(m0, mx0), mn1 = fmaxf(m1, mx1);
        float corr0 = exp2f(m0 - mn0), corr1 = exp2f(m1 - mn1);
        m0 = mn0; m1 = mn1;

        float sum0 = 0.f, sum1 = 0.f;
#pragma unroll
        for (int nt = 0; nt < 4; nt++) {
            float p00 = exp2f(sc[nt][0] - mn0);
            float p01 = exp2f(sc[nt][1] - mn0);
            float p10 = exp2f(sc[nt][2] - mn1);
            float p11 = exp2f(sc[nt][3] - mn1);
            sum0 += p00 + p01;
            sum1 += p10 + p11;
            *(float2*)&PS(w16 + g,     nt * 8 + 2 * t) =
                make_float2(f2tf32(p00), f2tf32(p01));
            *(float2*)&PS(w16 + g + 8, nt * 8 + 2 * t) =
                make_float2(f2tf32(p10), f2tf32(p11));
        }
        sum0 += __shfl_xor_sync(0xffffffffu, sum0, 1);
        sum0 += __shfl_xor_sync(0xffffffffu, sum0, 2);
        sum1 += __shfl_xor_sync(0xffffffffu, sum1, 1);
        sum1 += __shfl_xor_sync(0xffffffffu, sum1, 2);
        l0 = l0 * corr0 + sum0;
        l1 = l1 * corr1 + sum1;

#pragma unroll
        for (int d = 0; d < 8; d++) {
            o[d][0] *= corr0; o[d][1] *= corr0;
            o[d][2] *= corr1; o[d][3] *= corr1;
        }
        __syncwarp();

        // O[16x64] += P[16x32] @ V[32x64]
#pragma unroll
        for (int kk = 0; kk < 32; kk += 8) {
            uint32_t a[4];
            a[0] = __float_as_uint(PS(w16 + g,     kk + t));
            a[1] = __float_as_uint(PS(w16 + g + 8, kk + t));
            a[2] = __float_as_uint(PS(w16 + g,     kk + t + 4));
            a[3] = __float_as_uint(PS(w16 + g + 8, kk + t + 4));
#pragma unroll
            for (int d = 0; d < 8; d++) {
                uint32_t bf[2];
                bf[0] = __float_as_uint(VS(s, kk + t,     d * 8 + g));
                bf[1] = __float_as_uint(VS(s, kk + t + 4, d * 8 + g));
                MMA_TF32(o[d], a, bf);
            }
        }
        // next iteration's __syncthreads protects buffer reuse
    }

    float inv0 = 1.f / l0, inv1 = 1.f / l1;
    const int r0 = qt * 128 + w16 + g;
#pragma unroll
    for (int d = 0; d < 8; d++) {
        int col = h * HDIM + d * 8 + 2 * t;
        *(float2*)&g_ctx[((size_t)b * SEQ + r0) * HID + col] =
            make_float2(f2tf32(o[d][0] * inv0), f2tf32(o[d][1] * inv0));
        *(float2*)&g_ctx[((size_t)b * SEQ + r0 + 8) * HID + col] =
            make_float2(f2tf32(o[d][2] * inv1), f2tf32(o[d][3] * inv1));
    }
#undef QS
#undef KS
#undef VS
#undef PS
}

// ----------------------------------------------------------------------------
extern "C" void kernel_launch(void* const* d_in, const int* in_sizes, int n_in,
                              void* d_out, int out_size)
{
    const float* hs = (const float*)d_in[0];
    const float* Wq = (const float*)d_in[1];
    const float* bq = (const float*)d_in[2];
    const float* Wk = (const float*)d_in[3];
    const float* bk = (const float*)d_in[4];
    const float* Wv = (const float*)d_in[5];
    const float* bv = (const float*)d_in[6];
    const float* Wd = (const float*)d_in[7];
    const float* bd = (const float*)d_in[8];

    cudaFuncSetAttribute(mma_gemm<0>, cudaFuncAttributeMaxDynamicSharedMemorySize, GEMM_SMEM);
    cudaFuncSetAttribute(mma_gemm<1>, cudaFuncAttributeMaxDynamicSharedMemorySize, GEMM_SMEM);
    cudaFuncSetAttribute(attn_kernel, cudaFuncAttributeMaxDynamicSharedMemorySize, ATTN_SMEM);

    const int n4_hs = MROWS * HID / 4;
    const int n4_w  = HID * HID / 4;
    round_copy<<<(n4_hs + 255) / 256, 256>>>(hs, 0, n4_hs);
    round_copy<<<(n4_w  + 255) / 256, 256>>>(Wq, 1, n4_w);
    round_copy<<<(n4_w  + 255) / 256, 256>>>(Wk, 2, n4_w);
    round_copy<<<(n4_w  + 255) / 256, 256>>>(Wv, 3, n4_w);
    round_copy<<<(n4_w  + 255) / 256, 256>>>(Wd, 4, n4_w);

    const float qscale = 0.125f * 1.44269504088896f;   // 1/sqrt(D) * log2(e)
    dim3 gemmGrid(HID / 128, MROWS / 128);   // (8, 128)
    mma_gemm<1><<<gemmGrid, 256, GEMM_SMEM>>>(bq, nullptr, 0, qscale);
    mma_gemm<1><<<gemmGrid, 256, GEMM_SMEM>>>(bk, nullptr, 1, 1.f);
    mma_gemm<1><<<gemmGrid, 256, GEMM_SMEM>>>(bv, nullptr, 2, 1.f);

    attn_kernel<<<dim3(SEQ / 128, HEADS, BATCH), 256, ATTN_SMEM>>>();

    mma_gemm<0><<<gemmGrid, 256, GEMM_SMEM>>>(bd, (float*)d_out, 3, 1.f);
}

// round 7
// speedup vs baseline: 6.2626x; 1.9510x over previous
#include <cuda_runtime.h>
#include <cuda_fp16.h>
#include <cstdint>

// ============================================================================
// ViTMAE attention block: B=16, S=1024, HID=1024, HEADS=16, D=64, fp32 I/O.
// fp16 tensor cores (mma.m16n8k16, fp32 accum) + ldmatrix everywhere.
//   pre: x -> fp16 copy;  W* -> fp16 TRANSPOSED copies
//   q/k/v = x@W + b  (3-stage cp.async fp16 MMA; q pre-scaled; out fp16)
//   ctx = softmax(q k^T) v  (fp16 flash attention, fp32 softmax/accum)
//   out = ctx@Wd + bd  (fp32 output)
// ============================================================================

#define BATCH   16
#define SEQ     1024
#define HID     1024
#define HEADS   16
#define HDIM    64
#define MROWS   (BATCH * SEQ)   // 16384

__device__ __half g_q[(size_t)BATCH * HEADS * SEQ * HDIM];
__device__ __half g_k[(size_t)BATCH * HEADS * SEQ * HDIM];
__device__ __half g_v[(size_t)BATCH * HEADS * SEQ * HDIM];
__device__ __half g_ctx[(size_t)MROWS * HID];
__device__ __half g_hs[(size_t)MROWS * HID];
__device__ __half g_wq[(size_t)HID * HID];   // transposed: [n][k]
__device__ __half g_wk[(size_t)HID * HID];
__device__ __half g_wv[(size_t)HID * HID];
__device__ __half g_wd[(size_t)HID * HID];

__device__ __forceinline__ void cp16(void* smem, const void* gmem) {
    uint32_t s = (uint32_t)__cvta_generic_to_shared(smem);
    asm volatile("cp.async.cg.shared.global [%0], [%1], 16;" :: "r"(s), "l"(gmem));
}
#define CP_COMMIT() asm volatile("cp.async.commit_group;")
#define CP_WAIT(n)  asm volatile("cp.async.wait_group %0;" :: "n"(n))

__device__ __forceinline__ uint32_t smem_u32(const void* p) {
    return (uint32_t)__cvta_generic_to_shared(p);
}
__device__ __forceinline__ void ldsm4(uint32_t* r, uint32_t addr) {
    asm volatile("ldmatrix.sync.aligned.m8n8.x4.shared.b16 {%0,%1,%2,%3}, [%4];"
        : "=r"(r[0]), "=r"(r[1]), "=r"(r[2]), "=r"(r[3]) : "r"(addr));
}
__device__ __forceinline__ void ldsm2(uint32_t* r, uint32_t addr) {
    asm volatile("ldmatrix.sync.aligned.m8n8.x2.shared.b16 {%0,%1}, [%2];"
        : "=r"(r[0]), "=r"(r[1]) : "r"(addr));
}
__device__ __forceinline__ void ldsm2t(uint32_t* r, uint32_t addr) {
    asm volatile("ldmatrix.sync.aligned.m8n8.x2.trans.shared.b16 {%0,%1}, [%2];"
        : "=r"(r[0]), "=r"(r[1]) : "r"(addr));
}

#define MMA_F16(d, a, b)                                                      \
    asm volatile(                                                             \
        "mma.sync.aligned.m16n8k16.row.col.f32.f16.f16.f32 "                  \
        "{%0,%1,%2,%3}, {%4,%5,%6,%7}, {%8,%9}, {%0,%1,%2,%3};"               \
        : "+f"(d[0]), "+f"(d[1]), "+f"(d[2]), "+f"(d[3])                      \
        : "r"(a[0]), "r"(a[1]), "r"(a[2]), "r"(a[3]), "r"(b[0]), "r"(b[1]))

// ----------------------------------------------------------------------------
// pre-passes: fp32 -> fp16
// ----------------------------------------------------------------------------
__global__ __launch_bounds__(256) void round_copy_hs(const float* __restrict__ src, int n4)
{
    int i = blockIdx.x * blockDim.x + threadIdx.x;
    if (i < n4) {
        float4 v = ((const float4*)src)[i];
        ((__half2*)g_hs)[2 * i + 0] = __floats2half2_rn(v.x, v.y);
        ((__half2*)g_hs)[2 * i + 1] = __floats2half2_rn(v.z, v.w);
    }
}

// transposed fp16 weight copy: dst[n][k] = h(src[k][n])
__global__ __launch_bounds__(256) void wt_copy(const float* __restrict__ src, int which)
{
    __shared__ float tile[32][33];
    __half* dst = which == 0 ? g_wq : which == 1 ? g_wk :
                  which == 2 ? g_wv : g_wd;
    int tx = threadIdx.x & 31, ty = threadIdx.x >> 5;   // 32 x 8
    int x0 = blockIdx.x * 32, y0 = blockIdx.y * 32;
#pragma unroll
    for (int i = 0; i < 32; i += 8)
        tile[ty + i][tx] = src[(size_t)(y0 + ty + i) * HID + x0 + tx];
    __syncthreads();
#pragma unroll
    for (int i = 0; i < 32; i += 8)
        dst[(size_t)(x0 + ty + i) * HID + y0 + tx] = __float2half_rn(tile[tx][ty + i]);
}

// ----------------------------------------------------------------------------
// fp16 GEMM, 3-stage cp.async + ldmatrix.
// C[M,N] = A[M,K] @ Wt^T + bias.  BM=128, BN=128, BK=32, 256 thr (8 warps 2x4),
// warp tile 64x32 (4x4 m16n8k16 per k16-step).
// MODE 0: A=g_ctx, Wt=g_wd, out fp32 row-major (+bias).
// MODE 1: A=g_hs, Wt per which, out = h((acc+bias)*osc) scattered [B,H,S,D].
// smem: 3 stages x (A 128x40 + B 128x40) halves = 61440 B.
// ----------------------------------------------------------------------------
#define GEMM_SMEM (3 * 2 * 128 * 40 * 2)

template <int MODE>
__global__ __launch_bounds__(256) void h_gemm(
    const float* __restrict__ bias, float* __restrict__ outArg, int which,
    float osc)
{
    extern __shared__ __half smg[];
#define AS(s, r, c) smg[(s) * 5120 + (r) * 40 + (c)]
#define BS(s, r, c) smg[15360 + (s) * 5120 + (r) * 40 + (c)]

    const __half* __restrict__ A  = (MODE == 0) ? g_ctx : g_hs;
    const __half* __restrict__ Wt = which == 0 ? g_wq : which == 1 ? g_wk :
                                    which == 2 ? g_wv : g_wd;
    float* outF = outArg;
    __half* outH = (which == 0) ? g_q : (which == 1) ? g_k : g_v;

    const int tid = threadIdx.x;
    const int lane = tid & 31, warp = tid >> 5;
    const int wm = warp >> 2, wn = warp & 3;
    const int g = lane >> 2, t = lane & 3;
    const int row0 = blockIdx.y * 128;
    const int col0 = blockIdx.x * 128;

    float acc[4][4][4];
#pragma unroll
    for (int mt = 0; mt < 4; mt++)
#pragma unroll
        for (int nt = 0; nt < 4; nt++)
#pragma unroll
            for (int i = 0; i < 4; i++) acc[mt][nt][i] = 0.f;

    auto stage = [&](int s, int k0) {
#pragma unroll
        for (int j = 0; j < 2; j++) {
            int cid = tid + j * 256;          // 512 chunks each of A and B
            int r = cid >> 2, q = cid & 3;    // 128 rows x 4 x 8-half chunks
            cp16(&AS(s, r, q * 8), &A [(size_t)(row0 + r) * HID + k0 + q * 8]);
            cp16(&BS(s, r, q * 8), &Wt[(size_t)(col0 + r) * HID + k0 + q * 8]);
        }
    };

    const int NIT = HID / 32;   // 32
    stage(0, 0);  CP_COMMIT();
    stage(1, 32); CP_COMMIT();

    for (int it = 0; it < NIT; it++) {
        if (it + 1 < NIT) { CP_WAIT(1); } else { CP_WAIT(0); }
        __syncthreads();
        if (it + 2 < NIT) { stage((it + 2) % 3, (it + 2) * 32); CP_COMMIT(); }

        const int s = it % 3;
#pragma unroll
        for (int ks = 0; ks < 32; ks += 16) {
            uint32_t a[4][4], b[4][2];
#pragma unroll
            for (int mt = 0; mt < 4; mt++)
                ldsm4(a[mt], smem_u32(&AS(s, wm * 64 + mt * 16 + (lane & 15),
                                          ks + 8 * (lane >> 4))));
#pragma unroll
            for (int nt = 0; nt < 4; nt++)
                ldsm2(b[nt], smem_u32(&BS(s, wn * 32 + nt * 8 + (lane & 7),
                                          ks + 8 * ((lane >> 3) & 1))));
#pragma unroll
            for (int mt = 0; mt < 4; mt++)
#pragma unroll
                for (int nt = 0; nt < 4; nt++)
                    MMA_F16(acc[mt][nt], a[mt], b[nt]);
        }
    }

#pragma unroll
    for (int mt = 0; mt < 4; mt++) {
#pragma unroll
        for (int nt = 0; nt < 4; nt++) {
            int n = col0 + wn * 32 + nt * 8 + 2 * t;
            float b0 = bias[n], b1 = bias[n + 1];
#pragma unroll
            for (int hf = 0; hf < 2; hf++) {
                int m = row0 + wm * 64 + mt * 16 + g + hf * 8;
                float vx = acc[mt][nt][hf * 2 + 0] + b0;
                float vy = acc[mt][nt][hf * 2 + 1] + b1;
                if (MODE == 0) {
                    *(float2*)&outF[(size_t)m * HID + n] = make_float2(vx, vy);
                } else {
                    __half2 hv = __floats2half2_rn(vx * osc, vy * osc);
                    int bb = m >> 10, sq = m & 1023;
                    int h = n >> 6, d = n & 63;
                    *(__half2*)&outH[(((size_t)bb * HEADS + h) * SEQ + sq) * HDIM + d] = hv;
                }
            }
        }
    }
#undef AS
#undef BS
}

// ----------------------------------------------------------------------------
// fp16 flash attention, 3-stage cp.async K/V pipeline + ldmatrix.
// Grid (8 qtiles, 16 h, 16 b), 256 threads (8 warps, 16 q-rows each).
// Br=128, Bc=32, D=64. q pre-scaled by 0.125*log2e. fp32 softmax/accum.
// smem halves: Q 128x72 | K 3x32x72 | V 3x32x72 | P 128x40 = 56320 B.
// ----------------------------------------------------------------------------
#define ATTN_SMEM ((128 * 72 + 3 * 32 * 72 + 3 * 32 * 72 + 128 * 40) * 2)

__global__ __launch_bounds__(256) void attn_kernel()
{
    extern __shared__ __half sma[];
#define QS(r, c)    sma[(r) * 72 + (c)]
#define KS(s, r, c) sma[9216  + (s) * 2304 + (r) * 72 + (c)]
#define VS(s, r, c) sma[16128 + (s) * 2304 + (r) * 72 + (c)]
#define PS(r, c)    sma[23040 + (r) * 40 + (c)]

    const int tid = threadIdx.x;
    const int lane = tid & 31, warp = tid >> 5;
    const int g = lane >> 2, t = lane & 3;
    const int w16 = warp * 16;
    const int qt = blockIdx.x, h = blockIdx.y, b = blockIdx.z;
    const size_t bh = (size_t)b * HEADS + h;
    const __half* __restrict__ qb = g_q + (bh * SEQ + qt * 128) * HDIM;
    const __half* __restrict__ kb = g_k + bh * SEQ * HDIM;
    const __half* __restrict__ vb = g_v + bh * SEQ * HDIM;

    auto stageKV = [&](int s, int kc) {
        int r = tid >> 3, c = (tid & 7) * 8;     // 256 chunks each
        cp16(&KS(s, r, c), &kb[(size_t)(kc + r) * HDIM + c]);
        cp16(&VS(s, r, c), &vb[(size_t)(kc + r) * HDIM + c]);
    };

    // Q: 128x64 halves = 1024 16B chunks
#pragma unroll
    for (int j = 0; j < 4; j++) {
        int i = tid + j * 256;
        int r = i >> 3, c = (i & 7) * 8;
        cp16(&QS(r, c), &qb[(size_t)r * HDIM + c]);
    }
    stageKV(0, 0);  CP_COMMIT();
    stageKV(1, 32); CP_COMMIT();

    float m0 = -1e30f, m1 = -1e30f, l0 = 0.f, l1 = 0.f;
    float o[8][4];
#pragma unroll
    for (int d = 0; d < 8; d++)
#pragma unroll
        for (int i = 0; i < 4; i++) o[d][i] = 0.f;

    const int NKV = SEQ / 32;
    for (int it = 0; it < NKV; it++) {
        if (it + 1 < NKV) { CP_WAIT(1); } else { CP_WAIT(0); }
        __syncthreads();
        if (it + 2 < NKV) { stageKV((it + 2) % 3, (it + 2) * 32); CP_COMMIT(); }

        const int s = it % 3;

        // S[16x32] = Q_warp @ K^T
        float sc[4][4];
#pragma unroll
        for (int nt = 0; nt < 4; nt++)
#pragma unroll
            for (int i = 0; i < 4; i++) sc[nt][i] = 0.f;

#pragma unroll
        for (int ks = 0; ks < 64; ks += 16) {
            uint32_t a[4];
            ldsm4(a, smem_u32(&QS(w16 + (lane & 15), ks + 8 * (lane >> 4))));
#pragma unroll
            for (int nt = 0; nt < 4; nt++) {
                uint32_t bf[2];
                ldsm2(bf, smem_u32(&KS(s, nt * 8 + (lane & 7),
                                       ks + 8 * ((lane >> 3) & 1))));
                MMA_F16(sc[nt], a, bf);
            }
        }

        // online softmax in registers (rows g, g+8)
        float mx0 = -1e30f, mx1 = -1e30f;
#pragma unroll
        for (int nt = 0; nt < 4; nt++) {
            mx0 = fmaxf(mx0, fmaxf(sc[nt][0], sc[nt][1]));
            mx1 = fmaxf(mx1, fmaxf(sc[nt][2], sc[nt][3]));
        }
        mx0 = fmaxf(mx0, __shfl_xor_sync(0xffffffffu, mx0, 1));
        mx0 = fmaxf(mx0, __shfl_xor_sync(0xffffffffu, mx0, 2));
        mx1 = fmaxf(mx1, __shfl_xor_sync(0xffffffffu, mx1, 1));
        mx1 = fmaxf(mx1, __shfl_xor_sync(0xffffffffu, mx1, 2));

        float mn0 = fmaxf(m0, mx0), mn1 = fmaxf(m1, mx1);
        float corr0 = exp2f(m0 - mn0), corr1 = exp2f(m1 - mn1);
        m0 = mn0; m1 = mn1;

        float sum0 = 0.f, sum1 = 0.f;
#pragma unroll
        for (int nt = 0; nt < 4; nt++) {
            float p00 = exp2f(sc[nt][0] - mn0);
            float p01 = exp2f(sc[nt][1] - mn0);
            float p10 = exp2f(sc[nt][2] - mn1);
            float p11 = exp2f(sc[nt][3] - mn1);
            sum0 += p00 + p01;
            sum1 += p10 + p11;
            *(__half2*)&PS(w16 + g,     nt * 8 + 2 * t) = __floats2half2_rn(p00, p01);
            *(__half2*)&PS(w16 + g + 8, nt * 8 + 2 * t) = __floats2half2_rn(p10, p11);
        }
        sum0 += __shfl_xor_sync(0xffffffffu, sum0, 1);
        sum0 += __shfl_xor_sync(0xffffffffu, sum0, 2);
        sum1 += __shfl_xor_sync(0xffffffffu, sum1, 1);
        sum1 += __shfl_xor_sync(0xffffffffu, sum1, 2);
        l0 = l0 * corr0 + sum0;
        l1 = l1 * corr1 + sum1;

#pragma unroll
        for (int d = 0; d < 8; d++) {
            o[d][0] *= corr0; o[d][1] *= corr0;
            o[d][2] *= corr1; o[d][3] *= corr1;
        }
        __syncwarp();

        // O[16x64] += P[16x32] @ V[32x64]
#pragma unroll
        for (int kk = 0; kk < 32; kk += 16) {
            uint32_t a[4];
            ldsm4(a, smem_u32(&PS(w16 + (lane & 15), kk + 8 * (lane >> 4))));
#pragma unroll
            for (int dt = 0; dt < 8; dt++) {
                uint32_t bf[2];
                ldsm2t(bf, smem_u32(&VS(s, kk + (lane & 15), dt * 8)));
                MMA_F16(o[dt], a, bf);
            }
        }
    }

    float inv0 = 1.f / l0, inv1 = 1.f / l1;
    const int r0 = qt * 128 + w16 + g;
#pragma unroll
    for (int dt = 0; dt < 8; dt++) {
        int col = h * HDIM + dt * 8 + 2 * t;
        *(__half2*)&g_ctx[((size_t)b * SEQ + r0) * HID + col] =
            __floats2half2_rn(o[dt][0] * inv0, o[dt][1] * inv0);
        *(__half2*)&g_ctx[((size_t)b * SEQ + r0 + 8) * HID + col] =
            __floats2half2_rn(o[dt][2] * inv1, o[dt][3] * inv1);
    }
#undef QS
#undef KS
#undef VS
#undef PS
}

// ----------------------------------------------------------------------------
extern "C" void kernel_launch(void* const* d_in, const int* in_sizes, int n_in,
                              void* d_out, int out_size)
{
    const float* hs = (const float*)d_in[0];
    const float* Wq = (const float*)d_in[1];
    const float* bq = (const float*)d_in[2];
    const float* Wk = (const float*)d_in[3];
    const float* bk = (const float*)d_in[4];
    const float* Wv = (const float*)d_in[5];
    const float* bv = (const float*)d_in[6];
    const float* Wd = (const float*)d_in[7];
    const float* bd = (const float*)d_in[8];

    cudaFuncSetAttribute(h_gemm<0>, cudaFuncAttributeMaxDynamicSharedMemorySize, GEMM_SMEM);
    cudaFuncSetAttribute(h_gemm<1>, cudaFuncAttributeMaxDynamicSharedMemorySize, GEMM_SMEM);
    cudaFuncSetAttribute(attn_kernel, cudaFuncAttributeMaxDynamicSharedMemorySize, ATTN_SMEM);

    const int n4_hs = MROWS * HID / 4;
    round_copy_hs<<<(n4_hs + 255) / 256, 256>>>(hs, n4_hs);
    dim3 tGrid(HID / 32, HID / 32);
    wt_copy<<<tGrid, 256>>>(Wq, 0);
    wt_copy<<<tGrid, 256>>>(Wk, 1);
    wt_copy<<<tGrid, 256>>>(Wv, 2);
    wt_copy<<<tGrid, 256>>>(Wd, 3);

    const float qscale = 0.125f * 1.44269504088896f;   // 1/sqrt(D) * log2(e)
    dim3 gemmGrid(HID / 128, MROWS / 128);   // (8, 128)
    h_gemm<1><<<gemmGrid, 256, GEMM_SMEM>>>(bq, nullptr, 0, qscale);
    h_gemm<1><<<gemmGrid, 256, GEMM_SMEM>>>(bk, nullptr, 1, 1.f);
    h_gemm<1><<<gemmGrid, 256, GEMM_SMEM>>>(bv, nullptr, 2, 1.f);

    attn_kernel<<<dim3(SEQ / 128, HEADS, BATCH), 256, ATTN_SMEM>>>();

    h_gemm<0><<<gemmGrid, 256, GEMM_SMEM>>>(bd, (float*)d_out, 3, 1.f);
}